// round 11
// baseline (speedup 1.0000x reference)
#include <cuda_runtime.h>
#include <cuda_bf16.h>

#define NQ 8
#define FULLMASK 0xffffffffu

// One sample per 2 lanes; lane l owns matrix rows e = 4l .. 4l+3.
__global__ void __launch_bounds__(128, 6) acrobot_dyn_kernel(
    const float* __restrict__ q_in, const float* __restrict__ v_in,
    const float* __restrict__ u_in, const float* __restrict__ p,
    float* __restrict__ out, int Btot /* = B*NQ */)
{
    // ---- uniform coefficient tables (once per CTA) ----
    __shared__ float2 sCo[NQ][NQ + 1];  // (A, IsOrD) per (i,j); diag = (0, D[i])
    __shared__ float sGc[NQ];           // g * ls_k * (ms_suf_k - 0.5*ms_k)
    __shared__ float sTau[NQ];

    if (threadIdx.x == 0) {
        float ms[NQ], ls[NQ], ms_suf[NQ], Is_suf[NQ];
#pragma unroll
        for (int i = 0; i < NQ; i++) {
            ms[i] = p[i];
            ls[i] = p[NQ + i];
            sTau[i] = p[2 * NQ + 1 + i];
        }
        const float g = p[2 * NQ];
        float a = 0.0f, c = 0.0f;
#pragma unroll
        for (int i = NQ - 1; i >= 0; i--) {
            a += ms[i];
            c += ms[i] * ls[i] * ls[i] * (1.0f / 12.0f);
            ms_suf[i] = a;
            Is_suf[i] = c;
        }
#pragma unroll
        for (int i = 0; i < NQ; i++) {
            sGc[i] = g * ls[i] * (ms_suf[i] - 0.5f * ms[i]);
#pragma unroll
            for (int j = 0; j < NQ; j++) {
                if (i == j) {
                    sCo[i][j] = make_float2(
                        0.0f, ls[i] * ls[i] * (ms_suf[i] - 0.75f * ms[i]) + Is_suf[i]);
                } else {
                    const int mx = (i > j) ? i : j;
                    sCo[i][j] = make_float2(
                        ls[i] * ls[j] * (ms_suf[mx] - 0.5f * ms[mx]), Is_suf[mx]);
                }
            }
        }
    }
    __syncthreads();

    const int nQuads = Btot >> 2;                        // float4 elements
    int t4 = blockIdx.x * blockDim.x + threadIdx.x;      // quad index
    const bool valid = (t4 < nQuads);
    if (!valid) t4 = nQuads - 1;                         // keep shuffle pairs uniform
    const int l = threadIdx.x & 1;                       // lane within sample
    const int ebase = l * 4;                             // first owned row

    // ---- coalesced float4 loads ----
    const float4 q4 = ((const float4*)q_in)[t4];
    const float4 v4 = ((const float4*)v_in)[t4];
    const float vv[4] = {v4.x, v4.y, v4.z, v4.w};

    // ---- cumsums: per-thread prefix + one cross-lane shuffle each ----
    float cs[4], cv[4];
    cs[0] = q4.x; cs[1] = cs[0] + q4.y; cs[2] = cs[1] + q4.z; cs[3] = cs[2] + q4.w;
    cv[0] = v4.x; cv[1] = cv[0] + v4.y; cv[2] = cv[1] + v4.z; cv[3] = cv[2] + v4.w;
    {
        const float tq0 = __shfl_sync(FULLMASK, cs[3], 0, 2);  // lane-0 totals
        const float tv0 = __shfl_sync(FULLMASK, cv[3], 0, 2);
        if (l) {
#pragma unroll
            for (int i = 0; i < 4; i++) { cs[i] += tq0; cv[i] += tv0; }
        }
    }

    float sn[4], cn[4], vcv[4];
#pragma unroll
    for (int i = 0; i < 4; i++) {
        sn[i] = __sinf(cs[i]);
        cn[i] = __cosf(cs[i]);
        vcv[i] = vv[i] * cv[i];
    }

    // ---- build 4 owned matrix rows + Coriolis contractions ----
    float m[32];        // m[r*8+j] = M[ebase+r][j]
    float r1[4] = {0.f, 0.f, 0.f, 0.f}, r2[4] = {0.f, 0.f, 0.f, 0.f};
#pragma unroll
    for (int j = 0; j < NQ; j++) {
        const int jl = j >> 2, ji = j & 3;  // compile-time
        const float snj  = __shfl_sync(FULLMASK, sn[ji],  jl, 2);
        const float cnj  = __shfl_sync(FULLMASK, cn[ji],  jl, 2);
        const float vj   = __shfl_sync(FULLMASK, vv[ji],  jl, 2);
        const float vcvj = __shfl_sync(FULLMASK, vcv[ji], jl, 2);
#pragma unroll
        for (int r = 0; r < 4; r++) {
            const float2 c = sCo[ebase + r][j];
            const float cd = cn[r] * cnj + sn[r] * snj;   // cos(cs_e - cs_j)
            const float sd = sn[r] * cnj - cn[r] * snj;   // sin(cs_e - cs_j)
            m[r * 8 + j] = c.x * cd + c.y;                // diag handled by (A=0, D)
            const float T = c.x * sd;
            r1[r] += T * vj;
            r2[r] += T * vcvj;
        }
    }

    // ---- suffix sums across 8 elements (4/lane, one shuffle each) ----
    float suffR[4], suffG[4];
    {
        float pr = 0.f, pg = 0.f;
#pragma unroll
        for (int r = 3; r >= 0; r--) {
            pr += vv[r] * r1[r];
            pg += sGc[ebase + r] * sn[r];
            suffR[r] = pr;
            suffG[r] = pg;
        }
        const float tR1 = __shfl_sync(FULLMASK, suffR[0], 1, 2);  // lane-1 totals
        const float tG1 = __shfl_sync(FULLMASK, suffG[0], 1, 2);
        if (l == 0) {
#pragma unroll
            for (int r = 0; r < 4; r++) { suffR[r] += tR1; suffG[r] += tG1; }
        }
    }

    // ---- rhs ----
    const float4 u4 = ((const float4*)u_in)[t4];
    const float uu[4] = {u4.x, u4.y, u4.z, u4.w};
    float x[4];
#pragma unroll
    for (int r = 0; r < 4; r++) {
        const float Cv = -cv[r] * r1[r] + r2[r] + suffR[r];
        x[r] = sTau[ebase + r] * uu[r] - Cv - suffG[r];
    }

    // ---- Gaussian elimination (SPD, no pivoting) ----
    float dinv[4] = {0.f, 0.f, 0.f, 0.f};

    // Phase 1: pivots k=0..3 live on lane 0 -> broadcast pivot row
#pragma unroll
    for (int k = 0; k < 4; k++) {
        const float pivkk = __shfl_sync(FULLMASK, m[k * 8 + k], 0, 2);
        const float inv = __fdividef(1.0f, pivkk);
        if (l == 0) dinv[k] = inv;
        float f[4];
#pragma unroll
        for (int r = 0; r < 4; r++) f[r] = m[r * 8 + k] * inv;
#pragma unroll
        for (int j = k + 1; j < NQ; j++) {
            const float pj = __shfl_sync(FULLMASK, m[k * 8 + j], 0, 2);
#pragma unroll
            for (int r = 0; r < 4; r++)
                if (ebase + r > k) m[r * 8 + j] -= f[r] * pj;
        }
        const float px = __shfl_sync(FULLMASK, x[k], 0, 2);
#pragma unroll
        for (int r = 0; r < 4; r++)
            if (ebase + r > k) x[r] -= f[r] * px;
    }

    // Phase 2: pivots k=4..7 -- ALL active rows live on lane 1: fully local, zero shuffles
#pragma unroll
    for (int k = 4; k < NQ; k++) {
        const int ki = k - 4;
        const float inv = __fdividef(1.0f, m[ki * 8 + k]);  // lane 0 result unused
        if (l == 1) {
            dinv[ki] = inv;
#pragma unroll
            for (int r = ki + 1; r < 4; r++) {
                const float f = m[r * 8 + k] * inv;
#pragma unroll
                for (int j = k + 1; j < NQ; j++) m[r * 8 + j] -= f * m[ki * 8 + j];
                x[r] -= f * x[ki];
            }
        }
    }

    // ---- back substitution (one broadcast per k) ----
#pragma unroll
    for (int k = NQ - 1; k >= 0; k--) {
        const int ok = k >> 2, ki = k & 3;
        const float sOwn = x[ki] * dinv[ki];
        const float s = __shfl_sync(FULLMASK, sOwn, ok, 2);
        if (l == ok) x[ki] = s;
#pragma unroll
        for (int r = 0; r < 4; r++)
            if (r < k)                      // compile-time prune
                if (ebase + r < k)          // lane predicate
                    x[r] -= m[r * 8 + k] * s;
    }

    if (valid) ((float4*)out)[t4] = make_float4(x[0], x[1], x[2], x[3]);
}

extern "C" void kernel_launch(void* const* d_in, const int* in_sizes, int n_in,
                              void* d_out, int out_size) {
    const float* q = (const float*)d_in[0];
    const float* v = (const float*)d_in[1];
    const float* u = (const float*)d_in[2];
    const float* p = (const float*)d_in[3];
    float* out = (float*)d_out;
    const int Btot = in_sizes[0];       // B*NQ elements
    const int nThreads = Btot / 4;      // one thread per float4
    const int threads = 128;
    const int blocks = (nThreads + threads - 1) / threads;
    acrobot_dyn_kernel<<<blocks, threads>>>(q, v, u, p, out, Btot);
}

// round 12
// speedup vs baseline: 1.0045x; 1.0045x over previous
#include <cuda_runtime.h>
#include <cuda_bf16.h>

#define NQ 8
#define FULLMASK 0xffffffffu

// One sample per 2 lanes; lane l owns matrix rows ebase = 4l .. 4l+3.
// Both lanes redundantly load the whole sample (q,v) -> all trig local, few shuffles.
__global__ void __launch_bounds__(128, 6) acrobot_dyn_kernel(
    const float* __restrict__ q_in, const float* __restrict__ v_in,
    const float* __restrict__ u_in, const float* __restrict__ p,
    float* __restrict__ out, int Btot /* = B*NQ */)
{
    // ---- uniform coefficient tables (once per CTA) ----
    __shared__ float2 sCo[NQ][NQ + 1];  // (A, IsOrD) per (i,j); diag = (0, D[i])
    __shared__ float sGc[NQ];           // g * ls_k * (ms_suf_k - 0.5*ms_k)
    __shared__ float sTau[NQ];

    if (threadIdx.x == 0) {
        float ms[NQ], ls[NQ], ms_suf[NQ], Is_suf[NQ];
#pragma unroll
        for (int i = 0; i < NQ; i++) {
            ms[i] = p[i];
            ls[i] = p[NQ + i];
            sTau[i] = p[2 * NQ + 1 + i];
        }
        const float g = p[2 * NQ];
        float a = 0.0f, c = 0.0f;
#pragma unroll
        for (int i = NQ - 1; i >= 0; i--) {
            a += ms[i];
            c += ms[i] * ls[i] * ls[i] * (1.0f / 12.0f);
            ms_suf[i] = a;
            Is_suf[i] = c;
        }
#pragma unroll
        for (int i = 0; i < NQ; i++) {
            sGc[i] = g * ls[i] * (ms_suf[i] - 0.5f * ms[i]);
#pragma unroll
            for (int j = 0; j < NQ; j++) {
                if (i == j) {
                    sCo[i][j] = make_float2(
                        0.0f, ls[i] * ls[i] * (ms_suf[i] - 0.75f * ms[i]) + Is_suf[i]);
                } else {
                    const int mx = (i > j) ? i : j;
                    sCo[i][j] = make_float2(
                        ls[i] * ls[j] * (ms_suf[mx] - 0.5f * ms[mx]), Is_suf[mx]);
                }
            }
        }
    }
    __syncthreads();

    const int nQuads = Btot >> 2;
    int t4 = blockIdx.x * blockDim.x + threadIdx.x;
    const bool valid = (t4 < nQuads);
    if (!valid) t4 = nQuads - 1;
    const int l = threadIdx.x & 1;    // lane within sample
    const int ebase = l * 4;          // first owned row
    const int qlo = t4 & ~1;          // sample's low quad index

    // ---- load BOTH halves of the sample (partner hits the same L1 line) ----
    const float4 qA = ((const float4*)q_in)[qlo];
    const float4 qB = ((const float4*)q_in)[qlo + 1];
    const float4 vA = ((const float4*)v_in)[qlo];
    const float4 vB = ((const float4*)v_in)[qlo + 1];
    const float vf[NQ] = {vA.x, vA.y, vA.z, vA.w, vB.x, vB.y, vB.z, vB.w};

    // ---- full local cumsums + trig (zero shuffles) ----
    float sn[NQ], cn[NQ], w[NQ], cv_own[4];
    {
        const float qf[NQ] = {qA.x, qA.y, qA.z, qA.w, qB.x, qB.y, qB.z, qB.w};
        float aq = 0.0f, av = 0.0f;
        float cvf[NQ];
#pragma unroll
        for (int i = 0; i < NQ; i++) {
            aq += qf[i];
            av += vf[i];
            sn[i] = __sinf(aq);
            cn[i] = __cosf(aq);
            cvf[i] = av;
            w[i] = vf[i] * av;
        }
#pragma unroll
        for (int r = 0; r < 4; r++) cv_own[r] = l ? cvf[4 + r] : cvf[r];
    }

    // ---- build 4 owned matrix rows + Coriolis contractions (all local) ----
    float m[32];        // m[r*8+j] = M[ebase+r][j]
    float r1[4] = {0.f, 0.f, 0.f, 0.f}, r2[4] = {0.f, 0.f, 0.f, 0.f};
#pragma unroll
    for (int r = 0; r < 4; r++) {
        const float snr = l ? sn[4 + r] : sn[r];
        const float cnr = l ? cn[4 + r] : cn[r];
#pragma unroll
        for (int j = 0; j < NQ; j++) {
            const float2 c = sCo[ebase + r][j];
            const float cd = cnr * cn[j] + snr * sn[j];   // cos(cs_e - cs_j)
            const float sd = snr * cn[j] - cnr * sn[j];   // sin(cs_e - cs_j)
            m[r * 8 + j] = c.x * cd + c.y;                // diag: (A=0, D)
            const float T = c.x * sd;
            r1[r] += T * vf[j];
            r2[r] += T * w[j];
        }
    }

    // ---- gravity suffix: fully local; Coriolis suffix: one shuffle ----
    float suffG_own[4];
    {
        float sg[NQ];
        float acc = 0.0f;
#pragma unroll
        for (int i = NQ - 1; i >= 0; i--) {
            acc += sGc[i] * sn[i];
            sg[i] = acc;
        }
#pragma unroll
        for (int r = 0; r < 4; r++) suffG_own[r] = l ? sg[4 + r] : sg[r];
    }

    float suffR[4];
    {
        float pr = 0.0f;
#pragma unroll
        for (int r = 3; r >= 0; r--) {
            const float vr = l ? vf[4 + r] : vf[r];
            pr += vr * r1[r];
            suffR[r] = pr;
        }
        const float hi = __shfl_sync(FULLMASK, suffR[0], 1, 2);  // rows 4..7 total
        if (l == 0) {
#pragma unroll
            for (int r = 0; r < 4; r++) suffR[r] += hi;
        }
    }

    // ---- rhs ----
    const float4 u4 = ((const float4*)u_in)[t4];
    const float uu[4] = {u4.x, u4.y, u4.z, u4.w};
    float x[4];
#pragma unroll
    for (int r = 0; r < 4; r++) {
        const float Cv = -cv_own[r] * r1[r] + r2[r] + suffR[r];
        x[r] = sTau[ebase + r] * uu[r] - Cv - suffG_own[r];
    }

    // ---- GE phase 1: pivots 0..3 on lane 0 (broadcasts) ----
    float dinv[4] = {0.f, 0.f, 0.f, 0.f};
#pragma unroll
    for (int k = 0; k < 4; k++) {
        const float pivkk = __shfl_sync(FULLMASK, m[k * 8 + k], 0, 2);
        const float inv = __fdividef(1.0f, pivkk);
        if (l == 0) dinv[k] = inv;
        float f[4];
#pragma unroll
        for (int r = 0; r < 4; r++) f[r] = m[r * 8 + k] * inv;
#pragma unroll
        for (int j = k + 1; j < NQ; j++) {
            const float pj = __shfl_sync(FULLMASK, m[k * 8 + j], 0, 2);
#pragma unroll
            for (int r = 0; r < 4; r++)
                if (ebase + r > k) m[r * 8 + j] -= f[r] * pj;
        }
        const float px = __shfl_sync(FULLMASK, x[k], 0, 2);
#pragma unroll
        for (int r = 0; r < 4; r++)
            if (ebase + r > k) x[r] -= f[r] * px;
    }

    // ---- GE phase 2: pivots 4..7 entirely on lane 1 (zero shuffles) ----
#pragma unroll
    for (int k = 4; k < NQ; k++) {
        const int ki = k - 4;
        const float inv = __fdividef(1.0f, m[ki * 8 + k]);
        if (l == 1) {
            dinv[ki] = inv;
#pragma unroll
            for (int r = ki + 1; r < 4; r++) {
                const float f = m[r * 8 + k] * inv;
#pragma unroll
                for (int j = k + 1; j < NQ; j++) m[r * 8 + j] -= f * m[ki * 8 + j];
                x[r] -= f * x[ki];
            }
        }
    }

    // ---- backsub: lane 1 solves x4..7 locally, ships 4 values, lane 0 finishes ----
    if (l == 1) {
#pragma unroll
        for (int ki = 3; ki >= 0; ki--) {          // global row k = ki + 4
            float s = x[ki];
#pragma unroll
            for (int j = ki + 1; j < 4; j++) s -= m[ki * 8 + 4 + j] * x[j];
            x[ki] = s * dinv[ki];
        }
    }
    float xs[4];
#pragma unroll
    for (int ki = 0; ki < 4; ki++)
        xs[ki] = __shfl_sync(FULLMASK, x[ki], 1, 2);  // solved x[4..7]
    if (l == 0) {
#pragma unroll
        for (int r = 0; r < 4; r++) {
            float s = x[r];
#pragma unroll
            for (int ki = 0; ki < 4; ki++) s -= m[r * 8 + 4 + ki] * xs[ki];
            x[r] = s;
        }
#pragma unroll
        for (int r = 3; r >= 0; r--) {
            float s = x[r];
#pragma unroll
            for (int j = r + 1; j < 4; j++) s -= m[r * 8 + j] * x[j];
            x[r] = s * dinv[r];
        }
    }

    if (valid) ((float4*)out)[t4] = make_float4(x[0], x[1], x[2], x[3]);
}

extern "C" void kernel_launch(void* const* d_in, const int* in_sizes, int n_in,
                              void* d_out, int out_size) {
    const float* q = (const float*)d_in[0];
    const float* v = (const float*)d_in[1];
    const float* u = (const float*)d_in[2];
    const float* p = (const float*)d_in[3];
    float* out = (float*)d_out;
    const int Btot = in_sizes[0];       // B*NQ elements
    const int nThreads = Btot / 4;      // one thread per float4
    const int threads = 128;
    const int blocks = (nThreads + threads - 1) / threads;
    acrobot_dyn_kernel<<<blocks, threads>>>(q, v, u, p, out, Btot);
}